// round 1
// baseline (speedup 1.0000x reference)
#include <cuda_runtime.h>
#include <cuda_bf16.h>
#include <math.h>

// Problem constants
#define Bb 4
#define Tt 1024
#define Vv 50304
#define Ee 768
#define Ll 12
#define Hh 6
#define HDd 128
#define HIDh 3072
#define NTOK (Bb*Tt)          // 4096
#define EPS 1e-6f

// ---------------- scratch (static device globals; no allocation) -------------
__device__ float g_x [NTOK*Ee];
__device__ float g_x0[NTOK*Ee];
__device__ float g_h [NTOK*Ee];
__device__ float g_w [NTOK*Ee];
__device__ float g_o [NTOK*Ee];
__device__ float g_a [NTOK*HIDh];
__device__ float g_dots[(long long)Bb*Hh*Tt*Tt];   // 24 * 1024 * 1024

// ---------------- reductions -------------------------------------------------
__device__ __forceinline__ float warpSum(float v){
    #pragma unroll
    for (int o=16;o;o>>=1) v += __shfl_xor_sync(0xffffffffu, v, o);
    return v;
}
__device__ __forceinline__ float warpMax(float v){
    #pragma unroll
    for (int o=16;o;o>>=1) v = fmaxf(v, __shfl_xor_sync(0xffffffffu, v, o));
    return v;
}
__device__ __forceinline__ float blockSum(float v){
    __shared__ float sh[33];
    __syncthreads();
    int lane = threadIdx.x & 31, wid = threadIdx.x >> 5;
    v = warpSum(v);
    if (lane == 0) sh[wid] = v;
    __syncthreads();
    int nw = (blockDim.x + 31) >> 5;
    float r = (threadIdx.x < nw) ? sh[threadIdx.x] : 0.0f;
    if (wid == 0) r = warpSum(r);
    if (threadIdx.x == 0) sh[32] = r;
    __syncthreads();
    return sh[32];
}
__device__ __forceinline__ float blockMax(float v){
    __shared__ float sh[33];
    __syncthreads();
    int lane = threadIdx.x & 31, wid = threadIdx.x >> 5;
    v = warpMax(v);
    if (lane == 0) sh[wid] = v;
    __syncthreads();
    int nw = (blockDim.x + 31) >> 5;
    float r = (threadIdx.x < nw) ? sh[threadIdx.x] : -INFINITY;
    if (wid == 0) r = warpMax(r);
    if (threadIdx.x == 0) sh[32] = r;
    __syncthreads();
    return sh[32];
}

// ---------------- SGEMM 128x128x8, 256 threads, 8x8 per thread ---------------
// C[M,N] (op) A[M,K] x B ;  TB: B is [N,K] row-major (NT), else B is [K,N] (NN)
// EPI: 0 = store, 1 = accumulate into C, 2 = relu(acc - bias[n]) store
template<bool TB, int EPI>
__global__ __launch_bounds__(256)
void gemm_kernel(const float* __restrict__ A, const float* __restrict__ B,
                 float* __restrict__ C, const float* __restrict__ bias,
                 int M, int N, int K, int lda, int ldb, int ldc,
                 int zdiv,
                 long long sA1, long long sA2,
                 long long sB1, long long sB2,
                 long long sC1, long long sC2)
{
    int z  = blockIdx.z;
    int zq = z / zdiv, zr = z % zdiv;
    A += zq*sA1 + zr*sA2;
    B += zq*sB1 + zr*sB2;
    C += zq*sC1 + zr*sC2;

    __shared__ __align__(16) float As[8*128];
    __shared__ __align__(16) float Bs[8*128];

    const int bm = blockIdx.y * 128;
    const int bn = blockIdx.x * 128;
    const int tid = threadIdx.x;
    const int tx = tid & 15;      // N direction
    const int ty = tid >> 4;      // M direction

    float acc[8][8];
    #pragma unroll
    for (int i=0;i<8;i++)
        #pragma unroll
        for (int j=0;j<8;j++) acc[i][j]=0.0f;

    const int arow = tid >> 1;         // 0..127
    const int acol = (tid & 1) * 4;    // 0 or 4

    for (int k0 = 0; k0 < K; k0 += 8) {
        // A tile: 128 rows x 8 k, store transposed As[k][m]
        {
            float4 av = *(const float4*)(A + (long long)(bm+arow)*lda + k0 + acol);
            As[(acol+0)*128 + arow] = av.x;
            As[(acol+1)*128 + arow] = av.y;
            As[(acol+2)*128 + arow] = av.z;
            As[(acol+3)*128 + arow] = av.w;
        }
        if (TB) {
            float4 bv = *(const float4*)(B + (long long)(bn+arow)*ldb + k0 + acol);
            Bs[(acol+0)*128 + arow] = bv.x;
            Bs[(acol+1)*128 + arow] = bv.y;
            Bs[(acol+2)*128 + arow] = bv.z;
            Bs[(acol+3)*128 + arow] = bv.w;
        } else {
            int krow = tid >> 5;           // 0..7
            int c    = (tid & 31) * 4;     // 0..124
            *(float4*)&Bs[krow*128 + c] =
                *(const float4*)(B + (long long)(k0+krow)*ldb + bn + c);
        }
        __syncthreads();

        #pragma unroll
        for (int k=0;k<8;k++){
            float4 a0 = *(const float4*)&As[k*128 + ty*8    ];
            float4 a1 = *(const float4*)&As[k*128 + ty*8 + 4];
            float4 b0 = *(const float4*)&Bs[k*128 + tx*8    ];
            float4 b1 = *(const float4*)&Bs[k*128 + tx*8 + 4];
            float ar[8] = {a0.x,a0.y,a0.z,a0.w,a1.x,a1.y,a1.z,a1.w};
            float br[8] = {b0.x,b0.y,b0.z,b0.w,b1.x,b1.y,b1.z,b1.w};
            #pragma unroll
            for (int i=0;i<8;i++)
                #pragma unroll
                for (int j=0;j<8;j++)
                    acc[i][j] += ar[i]*br[j];
        }
        __syncthreads();
    }

    float bregs[8];
    if (EPI == 2) {
        #pragma unroll
        for (int j=0;j<8;j++) bregs[j] = bias[bn + tx*8 + j];
    }

    #pragma unroll
    for (int i=0;i<8;i++){
        float* cp = C + (long long)(bm + ty*8 + i)*ldc + bn + tx*8;
        if (EPI == 0) {
            *(float4*)(cp  ) = make_float4(acc[i][0],acc[i][1],acc[i][2],acc[i][3]);
            *(float4*)(cp+4) = make_float4(acc[i][4],acc[i][5],acc[i][6],acc[i][7]);
        } else if (EPI == 1) {
            float4 o0 = *(const float4*)(cp), o1 = *(const float4*)(cp+4);
            o0.x += acc[i][0]; o0.y += acc[i][1]; o0.z += acc[i][2]; o0.w += acc[i][3];
            o1.x += acc[i][4]; o1.y += acc[i][5]; o1.z += acc[i][6]; o1.w += acc[i][7];
            *(float4*)(cp) = o0; *(float4*)(cp+4) = o1;
        } else {
            float4 o0, o1;
            o0.x = fmaxf(acc[i][0]-bregs[0], 0.f);
            o0.y = fmaxf(acc[i][1]-bregs[1], 0.f);
            o0.z = fmaxf(acc[i][2]-bregs[2], 0.f);
            o0.w = fmaxf(acc[i][3]-bregs[3], 0.f);
            o1.x = fmaxf(acc[i][4]-bregs[4], 0.f);
            o1.y = fmaxf(acc[i][5]-bregs[5], 0.f);
            o1.z = fmaxf(acc[i][6]-bregs[6], 0.f);
            o1.w = fmaxf(acc[i][7]-bregs[7], 0.f);
            *(float4*)(cp) = o0; *(float4*)(cp+4) = o1;
        }
    }
}

// ---------------- elementwise kernels ---------------------------------------
// x = rmsnorm(wte[idx]); x0 = x.   grid=NTOK blocks, 256 threads
__global__ void embed_norm_kernel(const int* __restrict__ idx,
                                  const float* __restrict__ wte,
                                  float* __restrict__ x, float* __restrict__ x0)
{
    int t = blockIdx.x;
    int tok = idx[t];
    const float* row = wte + (long long)tok * Ee;
    long long base = (long long)t * Ee;
    float v[3]; float ss = 0.f;
    #pragma unroll
    for (int j=0;j<3;j++){ int c = threadIdx.x + j*256; float m = row[c]; v[j]=m; ss += m*m; }
    ss = blockSum(ss);
    float inv = rsqrtf(ss*(1.0f/Ee) + EPS);
    #pragma unroll
    for (int j=0;j<3;j++){ int c = threadIdx.x + j*256; float o = v[j]*inv; x[base+c]=o; x0[base+c]=o; }
}

// x = rl*x + xl*x0 (in-place); h = rmsnorm(x).   grid=NTOK, 256 threads
__global__ void mix_norm_kernel(float* __restrict__ x, const float* __restrict__ x0,
                                float* __restrict__ h,
                                const float* lamr, const float* lamx, int li)
{
    int t = blockIdx.x;
    float rl = lamr ? lamr[li] : 1.0f;
    float xl = lamx ? lamx[li] : 0.0f;
    long long base = (long long)t * Ee;
    float v[3]; float ss = 0.f;
    #pragma unroll
    for (int j=0;j<3;j++){
        int c = threadIdx.x + j*256;
        float m = rl*x[base+c] + xl*x0[base+c];
        v[j]=m; ss += m*m;
    }
    ss = blockSum(ss);
    float inv = rsqrtf(ss*(1.0f/Ee) + EPS);
    #pragma unroll
    for (int j=0;j<3;j++){
        int c = threadIdx.x + j*256;
        x[base+c] = v[j];
        h[base+c] = v[j]*inv;
    }
}

// rope + per-head rmsnorm, in place on w.  grid = NTOK*H blocks, 128 threads.
// (rope preserves per-pair sum of squares, so rms is computed pre-rope.)
__global__ void rope_norm_kernel(float* __restrict__ w)
{
    int n  = blockIdx.x / Hh;       // token index 0..4095
    int hh = blockIdx.x % Hh;
    int t  = n & (Tt-1);            // position within sequence
    float* base = w + (long long)n*Ee + hh*HDd;
    int d = threadIdx.x;            // 0..127
    __shared__ float s[HDd];
    float v = base[d];
    s[d] = v;
    float ss = blockSum(v*v);       // contains syncthreads; s[] visible after
    float inv = rsqrtf(ss*(1.0f/HDd) + EPS);
    float out;
    if (d < 64) {
        int j = d;
        float x1 = s[j], x2 = s[j+64];
        float fr = (float)t * powf(10000.0f, -((float)(2*j)) * (1.0f/128.0f));
        out = (x1*cosf(fr) + x2*sinf(fr)) * inv;
    } else {
        int j = d - 64;
        float x1 = s[j], x2 = s[d];
        float fr = (float)t * powf(10000.0f, -((float)(2*j)) * (1.0f/128.0f));
        out = (-x1*sinf(fr) + x2*cosf(fr)) * inv;
    }
    base[d] = out;
}

// causal softmax over dots rows. grid = B*H*T blocks (layout [z][q][k]), 256 thr.
__global__ void softmax_kernel(float* __restrict__ dots, float scale)
{
    long long r = blockIdx.x;            // z*T + q
    int q = (int)(r & (Tt-1));
    float* row = dots + r * Tt;
    int nv = q + 1;
    float vals[4];
    float m = -INFINITY;
    #pragma unroll
    for (int it=0; it<4; it++){
        int k = threadIdx.x + it*256;
        float v = (k < nv) ? row[k]*scale : -INFINITY;
        vals[it] = v;
        m = fmaxf(m, v);
    }
    m = blockMax(m);
    float sum = 0.f;
    #pragma unroll
    for (int it=0; it<4; it++){
        int k = threadIdx.x + it*256;
        float e = (k < nv) ? expf(vals[it]-m) : 0.0f;
        vals[it] = e; sum += e;
    }
    sum = blockSum(sum);
    float invs = 1.0f / sum;
    #pragma unroll
    for (int it=0; it<4; it++){
        int k = threadIdx.x + it*256;
        row[k] = vals[it]*invs;
    }
}

// ---------------- host-side launch helpers -----------------------------------
typedef long long ll;

static void launch_gemm(bool tb, int epi,
                        const float* A, const float* B, float* C, const float* bias,
                        int M, int N, int K, int lda, int ldb, int ldc,
                        int batch, int zdiv,
                        ll sA1, ll sA2, ll sB1, ll sB2, ll sC1, ll sC2)
{
    dim3 grid(N/128, M/128, batch);
    dim3 blk(256);
    if (tb) {
        if      (epi==0) gemm_kernel<true ,0><<<grid,blk>>>(A,B,C,bias,M,N,K,lda,ldb,ldc,zdiv,sA1,sA2,sB1,sB2,sC1,sC2);
        else if (epi==1) gemm_kernel<true ,1><<<grid,blk>>>(A,B,C,bias,M,N,K,lda,ldb,ldc,zdiv,sA1,sA2,sB1,sB2,sC1,sC2);
        else             gemm_kernel<true ,2><<<grid,blk>>>(A,B,C,bias,M,N,K,lda,ldb,ldc,zdiv,sA1,sA2,sB1,sB2,sC1,sC2);
    } else {
        if      (epi==0) gemm_kernel<false,0><<<grid,blk>>>(A,B,C,bias,M,N,K,lda,ldb,ldc,zdiv,sA1,sA2,sB1,sB2,sC1,sC2);
        else if (epi==1) gemm_kernel<false,1><<<grid,blk>>>(A,B,C,bias,M,N,K,lda,ldb,ldc,zdiv,sA1,sA2,sB1,sB2,sC1,sC2);
        else             gemm_kernel<false,2><<<grid,blk>>>(A,B,C,bias,M,N,K,lda,ldb,ldc,zdiv,sA1,sA2,sB1,sB2,sC1,sC2);
    }
}

extern "C" void kernel_launch(void* const* d_in, const int* in_sizes, int n_in,
                              void* d_out, int out_size)
{
    const int*   idx  = (const int*)  d_in[0];
    const float* wte  = (const float*)d_in[1];
    const float* lmh  = (const float*)d_in[2];
    const float* qkvw = (const float*)d_in[3];
    const float* cpjw = (const float*)d_in[4];
    const float* denc = (const float*)d_in[5];
    const float* ddec = (const float*)d_in[6];
    const float* thr  = (const float*)d_in[7];
    const float* lamr = (const float*)d_in[8];
    const float* lamx = (const float*)d_in[9];
    float* out = (float*)d_out;

    float *x, *x0, *h, *w, *o, *a, *dots;
    cudaGetSymbolAddress((void**)&x,    g_x);
    cudaGetSymbolAddress((void**)&x0,   g_x0);
    cudaGetSymbolAddress((void**)&h,    g_h);
    cudaGetSymbolAddress((void**)&w,    g_w);
    cudaGetSymbolAddress((void**)&o,    g_o);
    cudaGetSymbolAddress((void**)&a,    g_a);
    cudaGetSymbolAddress((void**)&dots, g_dots);

    const float scale = 0.08838834764831845f;   // HD^-0.5
    const ll TE = (ll)Tt*Ee;
    const ll TT = (ll)Tt*Tt;

    embed_norm_kernel<<<NTOK,256>>>(idx, wte, x, x0);

    for (int i=0;i<Ll;i++){
        // x = rl*x + xl*x0 ; h = rmsnorm(x)
        mix_norm_kernel<<<NTOK,256>>>(x, x0, h, lamr, lamx, i);

        // w = h @ qkv_w[i]^T
        launch_gemm(true,0, h, qkvw + (ll)i*Ee*Ee, w, nullptr,
                    NTOK, Ee, Ee, Ee, Ee, Ee, 1,1, 0,0,0,0,0,0);

        // rope + head rmsnorm in place
        rope_norm_kernel<<<NTOK*Hh,128>>>(w);

        // dots[z] = Wz Wz^T   (z = b*H + h), batched NT
        launch_gemm(true,0, w, w, dots, nullptr,
                    Tt, Tt, HDd, Ee, Ee, Tt, Bb*Hh, Hh,
                    TE, HDd, TE, HDd, (ll)Hh*TT, TT);

        // causal softmax (scale folded in)
        softmax_kernel<<<Bb*Hh*Tt,256>>>(dots, scale);

        // o[z] = P[z] @ V[z]   batched NN
        launch_gemm(false,0, dots, w, o, nullptr,
                    Tt, HDd, Tt, Tt, Ee, Ee, Bb*Hh, Hh,
                    (ll)Hh*TT, TT, TE, HDd, TE, HDd);

        // x += o @ cproj_w[i]^T
        launch_gemm(true,1, o, cpjw + (ll)i*Ee*Ee, x, nullptr,
                    NTOK, Ee, Ee, Ee, Ee, Ee, 1,1, 0,0,0,0,0,0);

        // h = rmsnorm(x)
        mix_norm_kernel<<<NTOK,256>>>(x, x0, h, nullptr, nullptr, 0);

        // a = relu(h @ denc_w[i]^T - thr[i])
        launch_gemm(true,2, h, denc + (ll)i*HIDh*Ee, a, thr + (ll)i*HIDh,
                    NTOK, HIDh, Ee, Ee, Ee, HIDh, 1,1, 0,0,0,0,0,0);

        // x += a @ ddec_w[i]^T
        launch_gemm(true,1, a, ddec + (ll)i*Ee*HIDh, x, nullptr,
                    NTOK, Ee, HIDh, HIDh, HIDh, Ee, 1,1, 0,0,0,0,0,0);
    }

    // final norm + lm head
    mix_norm_kernel<<<NTOK,256>>>(x, x0, h, nullptr, nullptr, 0);
    launch_gemm(true,0, h, lmh, out, nullptr,
                NTOK, Vv, Ee, Ee, Ee, Vv, 1,1, 0,0,0,0,0,0);
}